// round 14
// baseline (speedup 1.0000x reference)
#include <cuda_runtime.h>
#include <cuda_bf16.h>
#include <cstdint>
#include <math.h>

// Problem shape
constexpr int B = 8192, D = 1024, H = 2048;
constexpr int ND = B * D;
constexpr int NV4 = ND / 4;
constexpr float RTOL = 1e-3f, ATOL = 1e-3f, TARGET = 1.0f;
constexpr int NT = 256;
constexpr int GRIDX = 256;          // 1024/1024/512 tiles all divide evenly
constexpr int MAXSTEPS = 1000;

// dynamic SMEM layout (per pipeline stage)
constexpr int SA_H_OFF = 0;          // A hi: 128 rows * 80B
constexpr int SA_L_OFF = 10240;      // A lo
constexpr int SW_H_OFF = 20480;      // W hi: 32 rows * 272B
constexpr int SW_L_OFF = 29184;      // W lo
constexpr int STAGE_BYTES = 37888;   // total per stage
constexpr int DSM_BYTES = 2 * STAGE_BYTES;  // 75776

// ---------------- device state (static; no allocations) --------------------
__device__ float g_y[ND], g_y1[ND], g_ymid[ND];
__device__ float g_karr[7 * ND];
__device__ float g_cA[ND], g_cB[ND], g_cC[ND], g_cD[ND], g_cE[ND];
__device__ double g_red0[GRIDX], g_red1[GRIDX];
__device__ float g_t, g_dt, g_last_t, g_dt_used, g_h0, g_d1;
__device__ int   g_done, g_accept;
__device__ unsigned g_bar_count;
__device__ volatile unsigned g_bar_gen;

// bf16 hi/lo split storage
__device__ __nv_bfloat16 g_W1h[D * H], g_W1l[D * H];
__device__ __nv_bfloat16 g_W2h[H * H], g_W2l[H * H];
__device__ __nv_bfloat16 g_W3h[H * D], g_W3l[H * D];
__device__ __nv_bfloat16 g_xh[ND], g_xl[ND];
__device__ __nv_bfloat16 g_h1h[B * H], g_h1l[B * H];
__device__ __nv_bfloat16 g_h2h[B * H], g_h2l[B * H];

__constant__ float c_beta[6][6] = {
  {0.2f, 0.f, 0.f, 0.f, 0.f, 0.f},
  {(float)(3.0/40.0), (float)(9.0/40.0), 0.f, 0.f, 0.f, 0.f},
  {(float)(44.0/45.0), (float)(-56.0/15.0), (float)(32.0/9.0), 0.f, 0.f, 0.f},
  {(float)(19372.0/6561.0), (float)(-25360.0/2187.0), (float)(64448.0/6561.0),
   (float)(-212.0/729.0), 0.f, 0.f},
  {(float)(9017.0/3168.0), (float)(-355.0/33.0), (float)(46732.0/5247.0),
   (float)(49.0/176.0), (float)(-5103.0/18656.0), 0.f},
  {(float)(35.0/384.0), 0.f, (float)(500.0/1113.0), (float)(125.0/192.0),
   (float)(-2187.0/6784.0), (float)(11.0/84.0)},
};
__constant__ float c_ce[6] = {
  (float)(35.0/384.0 - 1951.0/21600.0),
  (float)(500.0/1113.0 - 22642.0/50085.0),
  (float)(125.0/192.0 - 451.0/720.0),
  (float)(-2187.0/6784.0 + 12231.0/42400.0),
  (float)(11.0/84.0 - 649.0/6300.0),
  (float)(-1.0/60.0),
};
__constant__ float c_cm[6] = {
  (float)(6025192743.0/30085553152.0/2.0),
  (float)(51252292925.0/65400821598.0/2.0),
  (float)(-2691868925.0/45128329728.0/2.0),
  (float)(187940372067.0/1594534317056.0/2.0),
  (float)(-1776094331.0/19743644256.0/2.0),
  (float)(11237099.0/235043384.0/2.0),
};

// ---------------- small helpers ---------------------------------------------
__device__ __forceinline__ void ld4(const float* p, int i, float* o) {
    float4 t = ((const float4*)p)[i];
    o[0] = t.x; o[1] = t.y; o[2] = t.z; o[3] = t.w;
}
__device__ __forceinline__ void st4(float* p, int i, const float* o) {
    float4 t;
    t.x = o[0]; t.y = o[1]; t.z = o[2]; t.w = o[3];
    ((float4*)p)[i] = t;
}

__device__ __forceinline__ unsigned smem_u32(const void* p) {
    unsigned r;
    asm("{ .reg .u64 t; cvta.to.shared.u64 t, %1; cvt.u32.u64 %0, t; }"
        : "=r"(r) : "l"(p));
    return r;
}

// ---------------- software grid barrier -------------------------------------
__device__ __forceinline__ void grid_sync() {
    __threadfence();
    __syncthreads();
    if (threadIdx.x == 0) {
        unsigned gen = g_bar_gen;
        if (atomicAdd(&g_bar_count, 1u) == gridDim.x - 1) {
            g_bar_count = 0;
            __threadfence();
            g_bar_gen = gen + 1;
        } else {
            while (g_bar_gen == gen) { __nanosleep(64); }
        }
    }
    __syncthreads();
    __threadfence();
}

// ---------------- tensor-core / cp.async primitives --------------------------
__device__ __forceinline__ void ldsm4(unsigned* r, unsigned addr) {
    asm volatile("ldmatrix.sync.aligned.m8n8.x4.shared.b16 {%0,%1,%2,%3}, [%4];"
                 : "=r"(r[0]), "=r"(r[1]), "=r"(r[2]), "=r"(r[3]) : "r"(addr));
}
__device__ __forceinline__ void ldsm2t(unsigned* r, unsigned addr) {
    asm volatile("ldmatrix.sync.aligned.m8n8.x2.trans.shared.b16 {%0,%1}, [%2];"
                 : "=r"(r[0]), "=r"(r[1]) : "r"(addr));
}
__device__ __forceinline__ void mma_bf16(float* d, const unsigned* a, const unsigned* b) {
    asm volatile(
        "mma.sync.aligned.m16n8k16.row.col.f32.bf16.bf16.f32 "
        "{%0,%1,%2,%3}, {%4,%5,%6,%7}, {%8,%9}, {%0,%1,%2,%3};"
        : "+f"(d[0]), "+f"(d[1]), "+f"(d[2]), "+f"(d[3])
        : "r"(a[0]), "r"(a[1]), "r"(a[2]), "r"(a[3]), "r"(b[0]), "r"(b[1]));
}
__device__ __forceinline__ void cp16(unsigned sa, const void* g) {
    asm volatile("cp.async.cg.shared.global [%0], [%1], 16;" :: "r"(sa), "l"(g));
}
__device__ __forceinline__ void cp_commit() {
    asm volatile("cp.async.commit_group;");
}
__device__ __forceinline__ void cp_wait1() {
    asm volatile("cp.async.wait_group 1;");
}
__device__ __forceinline__ void cp_wait0() {
    asm volatile("cp.async.wait_group 0;");
}

// issue async loads for one 32-wide K block into pipeline stage at sbase
__device__ __forceinline__ void issue_tile(
    const __nv_bfloat16* Ah, const __nv_bfloat16* Al,
    const __nv_bfloat16* Wh, const __nv_bfloat16* Wl,
    int bm, int bn, int kb, int K, int N, unsigned sbase, int tid)
{
    #pragma unroll
    for (int half = 0; half < 2; half++) {
        const int t = tid + half * 256;
        const int arow = t >> 2;
        const int ac4 = t & 3;
        const size_t aoff = (size_t)(bm + arow) * K + kb + ac4 * 8;
        cp16(sbase + SA_H_OFF + arow * 80 + ac4 * 16, Ah + aoff);
        cp16(sbase + SA_L_OFF + arow * 80 + ac4 * 16, Al + aoff);
        const int wrow = t >> 4;
        const int wcc = t & 15;
        const size_t woff = (size_t)(kb + wrow) * N + bn + wcc * 8;
        cp16(sbase + SW_H_OFF + wrow * 272 + wcc * 16, Wh + woff);
        cp16(sbase + SW_L_OFF + wrow * 272 + wcc * 16, Wl + woff);
    }
    cp_commit();
}

// ---------------- bf16-split GEMM phase (cp.async double-buffered) ----------
// C[M,N] = (Ah+Al)[M,K] @ (Wh+Wl)[K,N] + bias (+ReLU)
// Warp grid: 2 (M) x 4 (N); warp tile 64x32 -> mt=4, nt=4. 16 LDSM / 48 MMA per k16.
__device__ void gemm_tc(const __nv_bfloat16* Ah, const __nv_bfloat16* Al,
                        const __nv_bfloat16* Wh, const __nv_bfloat16* Wl,
                        const float* bias, float* Cf,
                        __nv_bfloat16* Ch, __nv_bfloat16* Cl,
                        int M, int N, int K, int relu)
{
    extern __shared__ char dsm[];
    const unsigned dbase = smem_u32(dsm);

    const int tid = threadIdx.x;
    const int lane = tid & 31;
    const int wrp = tid >> 5;
    const int warp_m = wrp & 1;          // 2 in M
    const int warp_n = wrp >> 1;         // 4 in N
    const int m_base = warp_m * 64;
    const int n_base = warp_n * 32;
    const int lrow = lane & 15;
    const int lcolh = (lane >> 4) << 3;

    const int ntn = N >> 7;
    const int ntiles = (M >> 7) * ntn;

    for (int tile = blockIdx.x; tile < ntiles; tile += gridDim.x) {
        const int bm = (tile / ntn) << 7;
        const int bn = (tile % ntn) << 7;

        float acc[4][4][4];
        #pragma unroll
        for (int mt = 0; mt < 4; mt++) {
            #pragma unroll
            for (int nt = 0; nt < 4; nt++) {
                #pragma unroll
                for (int q = 0; q < 4; q++) { acc[mt][nt][q] = 0.f; }
            }
        }

        issue_tile(Ah, Al, Wh, Wl, bm, bn, 0, K, N, dbase, tid);

        for (int kb = 0; kb < K; kb += 32) {
            const int st = (kb >> 5) & 1;
            const unsigned sb = dbase + st * STAGE_BYTES;
            if (kb + 32 < K) {
                issue_tile(Ah, Al, Wh, Wl, bm, bn, kb + 32, K, N,
                           dbase + (st ^ 1) * STAGE_BYTES, tid);
                cp_wait1();
            } else {
                cp_wait0();
            }
            __syncthreads();

            #pragma unroll
            for (int kh = 0; kh < 32; kh += 16) {
                unsigned rah[4][4];
                unsigned ral[4][4];
                #pragma unroll
                for (int mt = 0; mt < 4; mt++) {
                    const unsigned off =
                        (unsigned)(((m_base + mt * 16 + lrow) * 40 + kh + lcolh) * 2);
                    ldsm4(rah[mt], sb + SA_H_OFF + off);
                    ldsm4(ral[mt], sb + SA_L_OFF + off);
                }
                #pragma unroll
                for (int nt = 0; nt < 4; nt++) {
                    const unsigned boff =
                        (unsigned)(((kh + lrow) * 136 + n_base + nt * 8) * 2);
                    unsigned rbh[2];
                    unsigned rbl[2];
                    ldsm2t(rbh, sb + SW_H_OFF + boff);
                    ldsm2t(rbl, sb + SW_L_OFF + boff);
                    #pragma unroll
                    for (int mt = 0; mt < 4; mt++) {
                        mma_bf16(acc[mt][nt], rah[mt], rbh);
                        mma_bf16(acc[mt][nt], rah[mt], rbl);
                        mma_bf16(acc[mt][nt], ral[mt], rbh);
                    }
                }
            }
            __syncthreads();
        }

        const int er = lane >> 2;
        const int ec = (lane & 3) << 1;
        #pragma unroll
        for (int mt = 0; mt < 4; mt++) {
            #pragma unroll
            for (int nt = 0; nt < 4; nt++) {
                const int col = bn + n_base + nt * 8 + ec;
                const float bx = bias[col];
                const float by = bias[col + 1];
                #pragma unroll
                for (int hr = 0; hr < 2; hr++) {
                    const int row = bm + m_base + mt * 16 + er + hr * 8;
                    float v0 = acc[mt][nt][hr * 2 + 0] + bx;
                    float v1 = acc[mt][nt][hr * 2 + 1] + by;
                    if (relu) { v0 = fmaxf(v0, 0.f); v1 = fmaxf(v1, 0.f); }
                    if (Cf) {
                        *(float2*)(Cf + (size_t)row * N + col) = make_float2(v0, v1);
                    } else {
                        __nv_bfloat162 hv = __floats2bfloat162_rn(v0, v1);
                        float l0 = v0 - __bfloat162float(hv.x);
                        float l1 = v1 - __bfloat162float(hv.y);
                        *(__nv_bfloat162*)(Ch + (size_t)row * N + col) = hv;
                        *(__nv_bfloat162*)(Cl + (size_t)row * N + col) =
                            __floats2bfloat162_rn(l0, l1);
                    }
                }
            }
        }
    }
}

// f(split stage vec in g_xh/g_xl) -> kout (fp32)
__device__ void eval_f(float* kout, const float* b1, const float* b2, const float* b3)
{
    gemm_tc(g_xh, g_xl, g_W1h, g_W1l, b1, (float*)0, g_h1h, g_h1l, B, H, D, 1);
    grid_sync();
    gemm_tc(g_h1h, g_h1l, g_W2h, g_W2l, b2, (float*)0, g_h2h, g_h2l, B, H, H, 1);
    grid_sync();
    gemm_tc(g_h2h, g_h2l, g_W3h, g_W3l, b3, kout, (__nv_bfloat16*)0, (__nv_bfloat16*)0, B, D, H, 0);
    grid_sync();
}

// split float[4] into hi/lo bf16 at float4-index i of g_xh/g_xl
__device__ __forceinline__ void store_split(int i, const float* o) {
    __nv_bfloat162 h0 = __floats2bfloat162_rn(o[0], o[1]);
    __nv_bfloat162 h1 = __floats2bfloat162_rn(o[2], o[3]);
    __nv_bfloat162 l0 = __floats2bfloat162_rn(o[0] - __bfloat162float(h0.x),
                                              o[1] - __bfloat162float(h0.y));
    __nv_bfloat162 l1 = __floats2bfloat162_rn(o[2] - __bfloat162float(h1.x),
                                              o[3] - __bfloat162float(h1.y));
    ((__nv_bfloat162*)g_xh)[2 * i]     = h0;
    ((__nv_bfloat162*)g_xh)[2 * i + 1] = h1;
    ((__nv_bfloat162*)g_xl)[2 * i]     = l0;
    ((__nv_bfloat162*)g_xl)[2 * i + 1] = l1;
}

__device__ double block_reduce(double v) {
    __shared__ double sh[NT];
    sh[threadIdx.x] = v;
    __syncthreads();
    for (int s = NT / 2; s > 0; s >>= 1) {
        if (threadIdx.x < s) { sh[threadIdx.x] += sh[threadIdx.x + s]; }
        __syncthreads();
    }
    double r = sh[0];
    __syncthreads();
    return r;
}

__device__ double sum_partials(const double* part) {
    double s = 0.0;
    for (int i = threadIdx.x; i < (int)gridDim.x; i += NT) { s += part[i]; }
    return block_reduce(s);
}

__device__ void split_weights(const float* W, __nv_bfloat16* Wh, __nv_bfloat16* Wl,
                              int n, int gtid, int gstride)
{
    for (int i = gtid; i < n; i += gstride) {
        float w = W[i];
        __nv_bfloat16 h = __float2bfloat16(w);
        Wh[i] = h;
        Wl[i] = __float2bfloat16(w - __bfloat162float(h));
    }
}

// ---------------- the whole dopri5 solver as ONE kernel ---------------------
__global__ __launch_bounds__(NT, 2) void solver_kernel(
    const float* __restrict__ x,
    const float* __restrict__ W1, const float* __restrict__ b1,
    const float* __restrict__ W2, const float* __restrict__ b2,
    const float* __restrict__ W3, const float* __restrict__ b3,
    float* __restrict__ out)
{
    const int gtid = blockIdx.x * NT + threadIdx.x;
    const int gstride = gridDim.x * NT;

    // weights -> bf16 hi/lo; y = x (+ split)
    split_weights(W1, g_W1h, g_W1l, D * H, gtid, gstride);
    split_weights(W2, g_W2h, g_W2l, H * H, gtid, gstride);
    split_weights(W3, g_W3h, g_W3l, H * D, gtid, gstride);
    for (int i = gtid; i < NV4; i += gstride) {
        float v[4];
        ld4(x, i, v);
        st4(g_y, i, v);
        store_split(i, v);
    }
    grid_sync();

    // f0 = f(y) -> k0
    eval_f(g_karr, b1, b2, b3);

    // d0, d1 partials
    {
        double s0 = 0.0;
        double s1 = 0.0;
        for (int i = gtid; i < NV4; i += gstride) {
            float yv[4];
            float fv[4];
            ld4(g_y, i, yv);
            ld4(g_karr, i, fv);
            #pragma unroll
            for (int c = 0; c < 4; c++) {
                float sc = ATOL + RTOL * fabsf(yv[c]);
                float r0 = yv[c] / sc;
                float r1 = fv[c] / sc;
                s0 += (double)r0 * r0;
                s1 += (double)r1 * r1;
            }
        }
        s0 = block_reduce(s0);
        s1 = block_reduce(s1);
        if (threadIdx.x == 0) { g_red0[blockIdx.x] = s0; g_red1[blockIdx.x] = s1; }
    }
    grid_sync();
    if (blockIdx.x == 0) {
        double s0 = sum_partials(g_red0);
        double s1 = sum_partials(g_red1);
        if (threadIdx.x == 0) {
            float d0 = sqrtf((float)s0);
            float d1 = sqrtf((float)s1);
            g_d1 = d1;
            g_h0 = (d0 < 1e-5f || d1 < 1e-5f) ? 1e-6f : 0.01f * d0 / d1;
        }
    }
    grid_sync();

    // stage vec = y + h0*f0 ; f1 -> k1 slot
    {
        float h0v = g_h0;
        for (int i = gtid; i < NV4; i += gstride) {
            float yv[4];
            float fv[4];
            float o[4];
            ld4(g_y, i, yv);
            ld4(g_karr, i, fv);
            #pragma unroll
            for (int c = 0; c < 4; c++) { o[c] = yv[c] + h0v * fv[c]; }
            store_split(i, o);
        }
    }
    grid_sync();
    eval_f(g_karr + (size_t)ND, b1, b2, b3);

    // d2 -> initial dt
    {
        double s = 0.0;
        for (int i = gtid; i < NV4; i += gstride) {
            float yv[4];
            float fa[4];
            float fb[4];
            ld4(g_y, i, yv);
            ld4(g_karr, i, fa);
            ld4(g_karr + (size_t)ND, i, fb);
            #pragma unroll
            for (int c = 0; c < 4; c++) {
                float sc = ATOL + RTOL * fabsf(yv[c]);
                float r = (fb[c] - fa[c]) / sc;
                s += (double)r * r;
            }
        }
        s = block_reduce(s);
        if (threadIdx.x == 0) { g_red0[blockIdx.x] = s; }
    }
    grid_sync();
    if (blockIdx.x == 0) {
        double s = sum_partials(g_red0);
        if (threadIdx.x == 0) {
            float d2 = sqrtf((float)s) / g_h0;
            float d1 = g_d1;
            float h1v;
            if (d1 <= 1e-15f && d2 <= 1e-15f) {
                h1v = fmaxf(1e-6f, g_h0 * 1e-3f);
            } else {
                h1v = powf(0.01f / fmaxf(d1, d2), 0.2f);
            }
            g_dt = fminf(100.f * g_h0, h1v);
            g_t = 0.f; g_last_t = 0.f; g_done = 0; g_accept = 0;
        }
    }
    grid_sync();

    // adaptive loop
    for (int step = 0; step < MAXSTEPS; step++) {
        if (g_done) { break; }

        for (int s = 0; s < 6; s++) {
            float dt = g_dt;
            for (int i = gtid; i < NV4; i += gstride) {
                float accv[4] = {0.f, 0.f, 0.f, 0.f};
                for (int j = 0; j <= s; j++) {
                    float cj = c_beta[s][j];
                    float kv[4];
                    ld4(g_karr + (size_t)j * ND, i, kv);
                    #pragma unroll
                    for (int c = 0; c < 4; c++) { accv[c] += cj * kv[c]; }
                }
                float yv[4];
                float o[4];
                ld4(g_y, i, yv);
                #pragma unroll
                for (int c = 0; c < 4; c++) { o[c] = yv[c] + dt * accv[c]; }
                store_split(i, o);
                if (s == 5) { st4(g_y1, i, o); }
            }
            grid_sync();
            eval_f(g_karr + (size_t)(s + 1) * ND, b1, b2, b3);
        }

        // combine: error partials + y_mid
        {
            float dt = g_dt;
            double local = 0.0;
            for (int i = gtid; i < NV4; i += gstride) {
                float yv[4];
                float y1v[4];
                float mv[4];
                float a0[4];
                float a2[4];
                float a3[4];
                float a4[4];
                float a5[4];
                float a6[4];
                ld4(g_y, i, yv);
                ld4(g_y1, i, y1v);
                ld4(g_karr + 0 * (size_t)ND, i, a0);
                ld4(g_karr + 2 * (size_t)ND, i, a2);
                ld4(g_karr + 3 * (size_t)ND, i, a3);
                ld4(g_karr + 4 * (size_t)ND, i, a4);
                ld4(g_karr + 5 * (size_t)ND, i, a5);
                ld4(g_karr + 6 * (size_t)ND, i, a6);
                #pragma unroll
                for (int c = 0; c < 4; c++) {
                    float e = dt * (c_ce[0] * a0[c] + c_ce[1] * a2[c] + c_ce[2] * a3[c]
                                  + c_ce[3] * a4[c] + c_ce[4] * a5[c] + c_ce[5] * a6[c]);
                    mv[c] = yv[c] + dt * (c_cm[0] * a0[c] + c_cm[1] * a2[c] + c_cm[2] * a3[c]
                                        + c_cm[3] * a4[c] + c_cm[4] * a5[c] + c_cm[5] * a6[c]);
                    float tol = ATOL + RTOL * fmaxf(fabsf(yv[c]), fabsf(y1v[c]));
                    float r = e / tol;
                    local += (double)r * (double)r;
                }
                st4(g_ymid, i, mv);
            }
            local = block_reduce(local);
            if (threadIdx.x == 0) { g_red0[blockIdx.x] = local; }
        }
        grid_sync();

        // controller (block 0)
        if (blockIdx.x == 0) {
            double s = sum_partials(g_red0);
            if (threadIdx.x == 0) {
                float E2 = (float)(s / (double)ND);
                float ratio = sqrtf(E2);
                int acc_flag = (ratio <= 1.0f) ? 1 : 0;
                float dfac = (ratio < 1.0f) ? 1.0f : 0.2f;
                float factor = fminf(10.0f, fmaxf(0.9f * powf(ratio, -0.2f), dfac));
                float newdt = (ratio == 0.0f) ? g_dt * 10.0f : g_dt * factor;
                if (acc_flag) {
                    g_dt_used = g_dt;
                    g_last_t = g_t;
                    g_t = g_t + g_dt;
                    if (g_t >= TARGET) { g_done = 1; }
                }
                g_dt = newdt;
                g_accept = acc_flag;
            }
        }
        grid_sync();

        // accept: interp poly, y <- y1, k0 <- k6 (FSAL)
        if (g_accept) {
            float dtu = g_dt_used;
            for (int i = gtid; i < NV4; i += gstride) {
                float ya[4];
                float yb[4];
                float ym[4];
                float fa[4];
                float fb[4];
                float pA[4];
                float pB[4];
                float pC[4];
                float pD[4];
                float pE[4];
                ld4(g_y, i, ya);
                ld4(g_y1, i, yb);
                ld4(g_ymid, i, ym);
                ld4(g_karr + 0 * (size_t)ND, i, fa);
                ld4(g_karr + 6 * (size_t)ND, i, fb);
                #pragma unroll
                for (int c = 0; c < 4; c++) {
                    float dy0 = fa[c] * dtu;
                    float dy1 = fb[c] * dtu;
                    pA[c] = -2.f * dy0 + 2.f * dy1 - 8.f * ya[c] - 8.f * yb[c] + 16.f * ym[c];
                    pB[c] =  5.f * dy0 - 3.f * dy1 + 18.f * ya[c] + 14.f * yb[c] - 32.f * ym[c];
                    pC[c] = -4.f * dy0 + dy1 - 11.f * ya[c] - 5.f * yb[c] + 16.f * ym[c];
                    pD[c] = dy0;
                    pE[c] = ya[c];
                }
                st4(g_cA, i, pA);
                st4(g_cB, i, pB);
                st4(g_cC, i, pC);
                st4(g_cD, i, pD);
                st4(g_cE, i, pE);
                st4(g_y, i, yb);
                st4(g_karr + 0 * (size_t)ND, i, fb);
            }
        }
        grid_sync();
    }

    // dense-output interpolation at t = 1
    {
        float xr = (TARGET - g_last_t) / (g_t - g_last_t);
        for (int i = gtid; i < NV4; i += gstride) {
            float pA[4];
            float pB[4];
            float pC[4];
            float pD[4];
            float pE[4];
            float o[4];
            ld4(g_cA, i, pA);
            ld4(g_cB, i, pB);
            ld4(g_cC, i, pC);
            ld4(g_cD, i, pD);
            ld4(g_cE, i, pE);
            #pragma unroll
            for (int c = 0; c < 4; c++) {
                o[c] = (((pA[c] * xr + pB[c]) * xr + pC[c]) * xr + pD[c]) * xr + pE[c];
            }
            st4(out, i, o);
        }
    }
}

// ---------------- host: ONE launch -------------------------------------------
extern "C" void kernel_launch(void* const* d_in, const int* in_sizes, int n_in,
                              void* d_out, int out_size)
{
    const float* x  = (const float*)d_in[0];
    const float* W1 = (const float*)d_in[1];
    const float* b1 = (const float*)d_in[2];
    const float* W2 = (const float*)d_in[3];
    const float* b2 = (const float*)d_in[4];
    const float* W3 = (const float*)d_in[5];
    const float* b3 = (const float*)d_in[6];
    float* out = (float*)d_out;

    cudaFuncSetAttribute(solver_kernel,
                         cudaFuncAttributeMaxDynamicSharedMemorySize, DSM_BYTES);
    solver_kernel<<<GRIDX, NT, DSM_BYTES>>>(x, W1, b1, W2, b2, W3, b3, out);
}

// round 16
// speedup vs baseline: 1.0796x; 1.0796x over previous
#include <cuda_runtime.h>
#include <cuda_bf16.h>
#include <cstdint>
#include <math.h>

// Problem shape
constexpr int B = 8192, D = 1024, H = 2048;
constexpr int ND = B * D;
constexpr int NV4 = ND / 4;
constexpr float RTOL = 1e-3f, ATOL = 1e-3f, TARGET = 1.0f;
constexpr int NT = 256;
constexpr int GRIDX = 296;
constexpr int MAXSTEPS = 1000;

// dynamic SMEM layout (per pipeline stage)
constexpr int SA_H_OFF = 0;          // A hi: 128 rows * 80B
constexpr int SA_L_OFF = 10240;      // A lo
constexpr int SW_H_OFF = 20480;      // W hi: 32 rows * 272B
constexpr int SW_L_OFF = 29184;      // W lo
constexpr int STAGE_BYTES = 37888;   // total per stage
constexpr int DSM_BYTES = 2 * STAGE_BYTES;  // 75776

// ---------------- device state (static; no allocations) --------------------
__device__ float g_y[ND], g_y1[ND], g_ymid[ND];
__device__ float g_karr[7 * ND];
__device__ float g_cA[ND], g_cB[ND], g_cC[ND], g_cD[ND], g_cE[ND];
__device__ double g_red0[GRIDX], g_red1[GRIDX];
__device__ float g_t, g_dt, g_last_t, g_dt_used, g_h0, g_d1;
__device__ int   g_done, g_accept;
__device__ unsigned g_bar_count;
__device__ volatile unsigned g_bar_gen;

// bf16 hi/lo split storage
__device__ __nv_bfloat16 g_W1h[D * H], g_W1l[D * H];
__device__ __nv_bfloat16 g_W2h[H * H], g_W2l[H * H];
__device__ __nv_bfloat16 g_W3h[H * D], g_W3l[H * D];
__device__ __nv_bfloat16 g_xh[ND], g_xl[ND];
__device__ __nv_bfloat16 g_h1h[B * H], g_h1l[B * H];
__device__ __nv_bfloat16 g_h2h[B * H], g_h2l[B * H];

__constant__ float c_beta[6][6] = {
  {0.2f, 0.f, 0.f, 0.f, 0.f, 0.f},
  {(float)(3.0/40.0), (float)(9.0/40.0), 0.f, 0.f, 0.f, 0.f},
  {(float)(44.0/45.0), (float)(-56.0/15.0), (float)(32.0/9.0), 0.f, 0.f, 0.f},
  {(float)(19372.0/6561.0), (float)(-25360.0/2187.0), (float)(64448.0/6561.0),
   (float)(-212.0/729.0), 0.f, 0.f},
  {(float)(9017.0/3168.0), (float)(-355.0/33.0), (float)(46732.0/5247.0),
   (float)(49.0/176.0), (float)(-5103.0/18656.0), 0.f},
  {(float)(35.0/384.0), 0.f, (float)(500.0/1113.0), (float)(125.0/192.0),
   (float)(-2187.0/6784.0), (float)(11.0/84.0)},
};
__constant__ float c_ce[6] = {
  (float)(35.0/384.0 - 1951.0/21600.0),
  (float)(500.0/1113.0 - 22642.0/50085.0),
  (float)(125.0/192.0 - 451.0/720.0),
  (float)(-2187.0/6784.0 + 12231.0/42400.0),
  (float)(11.0/84.0 - 649.0/6300.0),
  (float)(-1.0/60.0),
};
__constant__ float c_cm[6] = {
  (float)(6025192743.0/30085553152.0/2.0),
  (float)(51252292925.0/65400821598.0/2.0),
  (float)(-2691868925.0/45128329728.0/2.0),
  (float)(187940372067.0/1594534317056.0/2.0),
  (float)(-1776094331.0/19743644256.0/2.0),
  (float)(11237099.0/235043384.0/2.0),
};

// ---------------- small helpers ---------------------------------------------
__device__ __forceinline__ void ld4(const float* p, int i, float* o) {
    float4 t = ((const float4*)p)[i];
    o[0] = t.x; o[1] = t.y; o[2] = t.z; o[3] = t.w;
}
__device__ __forceinline__ void st4(float* p, int i, const float* o) {
    float4 t;
    t.x = o[0]; t.y = o[1]; t.z = o[2]; t.w = o[3];
    ((float4*)p)[i] = t;
}

__device__ __forceinline__ unsigned smem_u32(const void* p) {
    unsigned r;
    asm("{ .reg .u64 t; cvta.to.shared.u64 t, %1; cvt.u32.u64 %0, t; }"
        : "=r"(r) : "l"(p));
    return r;
}

// ---------------- software grid barrier -------------------------------------
__device__ __forceinline__ void grid_sync() {
    __threadfence();
    __syncthreads();
    if (threadIdx.x == 0) {
        unsigned gen = g_bar_gen;
        if (atomicAdd(&g_bar_count, 1u) == gridDim.x - 1) {
            g_bar_count = 0;
            __threadfence();
            g_bar_gen = gen + 1;
        } else {
            while (g_bar_gen == gen) { __nanosleep(64); }
        }
    }
    __syncthreads();
    __threadfence();
}

// ---------------- tensor-core / cp.async primitives --------------------------
__device__ __forceinline__ void ldsm4(unsigned* r, unsigned addr) {
    asm volatile("ldmatrix.sync.aligned.m8n8.x4.shared.b16 {%0,%1,%2,%3}, [%4];"
                 : "=r"(r[0]), "=r"(r[1]), "=r"(r[2]), "=r"(r[3]) : "r"(addr));
}
__device__ __forceinline__ void ldsm2t(unsigned* r, unsigned addr) {
    asm volatile("ldmatrix.sync.aligned.m8n8.x2.trans.shared.b16 {%0,%1}, [%2];"
                 : "=r"(r[0]), "=r"(r[1]) : "r"(addr));
}
__device__ __forceinline__ void mma_bf16(float* d, const unsigned* a, const unsigned* b) {
    asm volatile(
        "mma.sync.aligned.m16n8k16.row.col.f32.bf16.bf16.f32 "
        "{%0,%1,%2,%3}, {%4,%5,%6,%7}, {%8,%9}, {%0,%1,%2,%3};"
        : "+f"(d[0]), "+f"(d[1]), "+f"(d[2]), "+f"(d[3])
        : "r"(a[0]), "r"(a[1]), "r"(a[2]), "r"(a[3]), "r"(b[0]), "r"(b[1]));
}
__device__ __forceinline__ void cp16(unsigned sa, const void* g) {
    asm volatile("cp.async.cg.shared.global [%0], [%1], 16;" :: "r"(sa), "l"(g));
}
__device__ __forceinline__ void cp_commit() {
    asm volatile("cp.async.commit_group;");
}
__device__ __forceinline__ void cp_wait1() {
    asm volatile("cp.async.wait_group 1;");
}
__device__ __forceinline__ void cp_wait0() {
    asm volatile("cp.async.wait_group 0;");
}

// issue async loads for one 32-wide K block into pipeline stage at sbase
__device__ __forceinline__ void issue_tile(
    const __nv_bfloat16* Ah, const __nv_bfloat16* Al,
    const __nv_bfloat16* Wh, const __nv_bfloat16* Wl,
    int bm, int bn, int kb, int K, int N, unsigned sbase, int tid)
{
    #pragma unroll
    for (int half = 0; half < 2; half++) {
        const int t = tid + half * 256;
        const int arow = t >> 2;
        const int ac4 = t & 3;
        const size_t aoff = (size_t)(bm + arow) * K + kb + ac4 * 8;
        cp16(sbase + SA_H_OFF + arow * 80 + ac4 * 16, Ah + aoff);
        cp16(sbase + SA_L_OFF + arow * 80 + ac4 * 16, Al + aoff);
        const int wrow = t >> 4;
        const int wcc = t & 15;
        const size_t woff = (size_t)(kb + wrow) * N + bn + wcc * 8;
        cp16(sbase + SW_H_OFF + wrow * 272 + wcc * 16, Wh + woff);
        cp16(sbase + SW_L_OFF + wrow * 272 + wcc * 16, Wl + woff);
    }
    cp_commit();
}

// ---------------- bf16-split GEMM phase (cp.async double-buffered) ----------
// C[M,N] = (Ah+Al)[M,K] @ (Wh+Wl)[K,N] + bias (+ReLU)
// Warp grid 4(M) x 2(N), warp tile 32x64 (the R11 winner layout).
// Cross-tile prefetch: during the last K-block of a tile, the NEXT tile's k0
// is issued into the free stage so it streams during the epilogue.
__device__ void gemm_tc(const __nv_bfloat16* Ah, const __nv_bfloat16* Al,
                        const __nv_bfloat16* Wh, const __nv_bfloat16* Wl,
                        const float* bias, float* Cf,
                        __nv_bfloat16* Ch, __nv_bfloat16* Cl,
                        int M, int N, int K, int relu)
{
    extern __shared__ char dsm[];
    const unsigned dbase = smem_u32(dsm);

    const int tid = threadIdx.x;
    const int lane = tid & 31;
    const int wrp = tid >> 5;
    const int warp_m = wrp >> 1;
    const int warp_n = wrp & 1;
    const int m_base = warp_m * 32;
    const int n_base = warp_n * 64;
    const int lrow = lane & 15;
    const int lcolh = (lane >> 4) << 3;

    const int ntn = N >> 7;
    const int ntiles = (M >> 7) * ntn;

    bool prefetched = false;   // next tile's k0 already issued into stage 0?

    for (int tile = blockIdx.x; tile < ntiles; tile += gridDim.x) {
        const int bm = (tile / ntn) << 7;
        const int bn = (tile % ntn) << 7;

        float acc[2][8][4];
        #pragma unroll
        for (int mt = 0; mt < 2; mt++) {
            #pragma unroll
            for (int nt = 0; nt < 8; nt++) {
                #pragma unroll
                for (int q = 0; q < 4; q++) { acc[mt][nt][q] = 0.f; }
            }
        }

        if (!prefetched) {
            issue_tile(Ah, Al, Wh, Wl, bm, bn, 0, K, N, dbase, tid);
        }
        prefetched = false;

        for (int kb = 0; kb < K; kb += 32) {
            const int st = (kb >> 5) & 1;
            const unsigned sb = dbase + st * STAGE_BYTES;
            if (kb + 32 < K) {
                issue_tile(Ah, Al, Wh, Wl, bm, bn, kb + 32, K, N,
                           dbase + (st ^ 1) * STAGE_BYTES, tid);
                cp_wait1();
            } else {
                // last K-block: prefetch next tile's k0 into the free stage.
                // nK is even (K = 1024 / 2048), so st == 1 here and st^1 == 0,
                // matching the next tile's stage-0 expectation.
                const int ntile = tile + gridDim.x;
                if (ntile < ntiles) {
                    const int nbm = (ntile / ntn) << 7;
                    const int nbn = (ntile % ntn) << 7;
                    issue_tile(Ah, Al, Wh, Wl, nbm, nbn, 0, K, N,
                               dbase + (st ^ 1) * STAGE_BYTES, tid);
                    prefetched = true;
                    cp_wait1();
                } else {
                    cp_wait0();
                }
            }
            __syncthreads();

            #pragma unroll
            for (int kh = 0; kh < 32; kh += 16) {
                unsigned rah[2][4];
                unsigned ral[2][4];
                #pragma unroll
                for (int mt = 0; mt < 2; mt++) {
                    const unsigned off =
                        (unsigned)(((m_base + mt * 16 + lrow) * 40 + kh + lcolh) * 2);
                    ldsm4(rah[mt], sb + SA_H_OFF + off);
                    ldsm4(ral[mt], sb + SA_L_OFF + off);
                }
                #pragma unroll
                for (int nt = 0; nt < 8; nt++) {
                    const unsigned boff =
                        (unsigned)(((kh + lrow) * 136 + n_base + nt * 8) * 2);
                    unsigned rbh[2];
                    unsigned rbl[2];
                    ldsm2t(rbh, sb + SW_H_OFF + boff);
                    ldsm2t(rbl, sb + SW_L_OFF + boff);
                    #pragma unroll
                    for (int mt = 0; mt < 2; mt++) {
                        mma_bf16(acc[mt][nt], rah[mt], rbh);
                        mma_bf16(acc[mt][nt], rah[mt], rbl);
                        mma_bf16(acc[mt][nt], ral[mt], rbh);
                    }
                }
            }
            __syncthreads();
        }

        const int er = lane >> 2;
        const int ec = (lane & 3) << 1;
        #pragma unroll
        for (int mt = 0; mt < 2; mt++) {
            #pragma unroll
            for (int nt = 0; nt < 8; nt++) {
                const int col = bn + n_base + nt * 8 + ec;
                const float bx = bias[col];
                const float by = bias[col + 1];
                #pragma unroll
                for (int hr = 0; hr < 2; hr++) {
                    const int row = bm + m_base + mt * 16 + er + hr * 8;
                    float v0 = acc[mt][nt][hr * 2 + 0] + bx;
                    float v1 = acc[mt][nt][hr * 2 + 1] + by;
                    if (relu) { v0 = fmaxf(v0, 0.f); v1 = fmaxf(v1, 0.f); }
                    if (Cf) {
                        *(float2*)(Cf + (size_t)row * N + col) = make_float2(v0, v1);
                    } else {
                        __nv_bfloat162 hv = __floats2bfloat162_rn(v0, v1);
                        float l0 = v0 - __bfloat162float(hv.x);
                        float l1 = v1 - __bfloat162float(hv.y);
                        *(__nv_bfloat162*)(Ch + (size_t)row * N + col) = hv;
                        *(__nv_bfloat162*)(Cl + (size_t)row * N + col) =
                            __floats2bfloat162_rn(l0, l1);
                    }
                }
            }
        }
    }
}

// f(split stage vec in g_xh/g_xl) -> kout (fp32)
__device__ void eval_f(float* kout, const float* b1, const float* b2, const float* b3)
{
    gemm_tc(g_xh, g_xl, g_W1h, g_W1l, b1, (float*)0, g_h1h, g_h1l, B, H, D, 1);
    grid_sync();
    gemm_tc(g_h1h, g_h1l, g_W2h, g_W2l, b2, (float*)0, g_h2h, g_h2l, B, H, H, 1);
    grid_sync();
    gemm_tc(g_h2h, g_h2l, g_W3h, g_W3l, b3, kout, (__nv_bfloat16*)0, (__nv_bfloat16*)0, B, D, H, 0);
    grid_sync();
}

// split float[4] into hi/lo bf16 at float4-index i of g_xh/g_xl
__device__ __forceinline__ void store_split(int i, const float* o) {
    __nv_bfloat162 h0 = __floats2bfloat162_rn(o[0], o[1]);
    __nv_bfloat162 h1 = __floats2bfloat162_rn(o[2], o[3]);
    __nv_bfloat162 l0 = __floats2bfloat162_rn(o[0] - __bfloat162float(h0.x),
                                              o[1] - __bfloat162float(h0.y));
    __nv_bfloat162 l1 = __floats2bfloat162_rn(o[2] - __bfloat162float(h1.x),
                                              o[3] - __bfloat162float(h1.y));
    ((__nv_bfloat162*)g_xh)[2 * i]     = h0;
    ((__nv_bfloat162*)g_xh)[2 * i + 1] = h1;
    ((__nv_bfloat162*)g_xl)[2 * i]     = l0;
    ((__nv_bfloat162*)g_xl)[2 * i + 1] = l1;
}

__device__ double block_reduce(double v) {
    __shared__ double sh[NT];
    sh[threadIdx.x] = v;
    __syncthreads();
    for (int s = NT / 2; s > 0; s >>= 1) {
        if (threadIdx.x < s) { sh[threadIdx.x] += sh[threadIdx.x + s]; }
        __syncthreads();
    }
    double r = sh[0];
    __syncthreads();
    return r;
}

__device__ double sum_partials(const double* part) {
    double s = 0.0;
    for (int i = threadIdx.x; i < (int)gridDim.x; i += NT) { s += part[i]; }
    return block_reduce(s);
}

__device__ void split_weights(const float* W, __nv_bfloat16* Wh, __nv_bfloat16* Wl,
                              int n, int gtid, int gstride)
{
    for (int i = gtid; i < n; i += gstride) {
        float w = W[i];
        __nv_bfloat16 h = __float2bfloat16(w);
        Wh[i] = h;
        Wl[i] = __float2bfloat16(w - __bfloat162float(h));
    }
}

// ---------------- the whole dopri5 solver as ONE kernel ---------------------
__global__ __launch_bounds__(NT, 2) void solver_kernel(
    const float* __restrict__ x,
    const float* __restrict__ W1, const float* __restrict__ b1,
    const float* __restrict__ W2, const float* __restrict__ b2,
    const float* __restrict__ W3, const float* __restrict__ b3,
    float* __restrict__ out)
{
    const int gtid = blockIdx.x * NT + threadIdx.x;
    const int gstride = gridDim.x * NT;

    // weights -> bf16 hi/lo; y = x (+ split)
    split_weights(W1, g_W1h, g_W1l, D * H, gtid, gstride);
    split_weights(W2, g_W2h, g_W2l, H * H, gtid, gstride);
    split_weights(W3, g_W3h, g_W3l, H * D, gtid, gstride);
    for (int i = gtid; i < NV4; i += gstride) {
        float v[4];
        ld4(x, i, v);
        st4(g_y, i, v);
        store_split(i, v);
    }
    grid_sync();

    // f0 = f(y) -> k0
    eval_f(g_karr, b1, b2, b3);

    // d0, d1 partials
    {
        double s0 = 0.0;
        double s1 = 0.0;
        for (int i = gtid; i < NV4; i += gstride) {
            float yv[4];
            float fv[4];
            ld4(g_y, i, yv);
            ld4(g_karr, i, fv);
            #pragma unroll
            for (int c = 0; c < 4; c++) {
                float sc = ATOL + RTOL * fabsf(yv[c]);
                float r0 = yv[c] / sc;
                float r1 = fv[c] / sc;
                s0 += (double)r0 * r0;
                s1 += (double)r1 * r1;
            }
        }
        s0 = block_reduce(s0);
        s1 = block_reduce(s1);
        if (threadIdx.x == 0) { g_red0[blockIdx.x] = s0; g_red1[blockIdx.x] = s1; }
    }
    grid_sync();
    if (blockIdx.x == 0) {
        double s0 = sum_partials(g_red0);
        double s1 = sum_partials(g_red1);
        if (threadIdx.x == 0) {
            float d0 = sqrtf((float)s0);
            float d1 = sqrtf((float)s1);
            g_d1 = d1;
            g_h0 = (d0 < 1e-5f || d1 < 1e-5f) ? 1e-6f : 0.01f * d0 / d1;
        }
    }
    grid_sync();

    // stage vec = y + h0*f0 ; f1 -> k1 slot
    {
        float h0v = g_h0;
        for (int i = gtid; i < NV4; i += gstride) {
            float yv[4];
            float fv[4];
            float o[4];
            ld4(g_y, i, yv);
            ld4(g_karr, i, fv);
            #pragma unroll
            for (int c = 0; c < 4; c++) { o[c] = yv[c] + h0v * fv[c]; }
            store_split(i, o);
        }
    }
    grid_sync();
    eval_f(g_karr + (size_t)ND, b1, b2, b3);

    // d2 -> initial dt
    {
        double s = 0.0;
        for (int i = gtid; i < NV4; i += gstride) {
            float yv[4];
            float fa[4];
            float fb[4];
            ld4(g_y, i, yv);
            ld4(g_karr, i, fa);
            ld4(g_karr + (size_t)ND, i, fb);
            #pragma unroll
            for (int c = 0; c < 4; c++) {
                float sc = ATOL + RTOL * fabsf(yv[c]);
                float r = (fb[c] - fa[c]) / sc;
                s += (double)r * r;
            }
        }
        s = block_reduce(s);
        if (threadIdx.x == 0) { g_red0[blockIdx.x] = s; }
    }
    grid_sync();
    if (blockIdx.x == 0) {
        double s = sum_partials(g_red0);
        if (threadIdx.x == 0) {
            float d2 = sqrtf((float)s) / g_h0;
            float d1 = g_d1;
            float h1v;
            if (d1 <= 1e-15f && d2 <= 1e-15f) {
                h1v = fmaxf(1e-6f, g_h0 * 1e-3f);
            } else {
                h1v = powf(0.01f / fmaxf(d1, d2), 0.2f);
            }
            g_dt = fminf(100.f * g_h0, h1v);
            g_t = 0.f; g_last_t = 0.f; g_done = 0; g_accept = 0;
        }
    }
    grid_sync();

    // adaptive loop
    for (int step = 0; step < MAXSTEPS; step++) {
        if (g_done) { break; }

        for (int s = 0; s < 6; s++) {
            float dt = g_dt;
            for (int i = gtid; i < NV4; i += gstride) {
                float accv[4] = {0.f, 0.f, 0.f, 0.f};
                for (int j = 0; j <= s; j++) {
                    float cj = c_beta[s][j];
                    float kv[4];
                    ld4(g_karr + (size_t)j * ND, i, kv);
                    #pragma unroll
                    for (int c = 0; c < 4; c++) { accv[c] += cj * kv[c]; }
                }
                float yv[4];
                float o[4];
                ld4(g_y, i, yv);
                #pragma unroll
                for (int c = 0; c < 4; c++) { o[c] = yv[c] + dt * accv[c]; }
                store_split(i, o);
                if (s == 5) { st4(g_y1, i, o); }
            }
            grid_sync();
            eval_f(g_karr + (size_t)(s + 1) * ND, b1, b2, b3);
        }

        // combine: error partials + y_mid
        {
            float dt = g_dt;
            double local = 0.0;
            for (int i = gtid; i < NV4; i += gstride) {
                float yv[4];
                float y1v[4];
                float mv[4];
                float a0[4];
                float a2[4];
                float a3[4];
                float a4[4];
                float a5[4];
                float a6[4];
                ld4(g_y, i, yv);
                ld4(g_y1, i, y1v);
                ld4(g_karr + 0 * (size_t)ND, i, a0);
                ld4(g_karr + 2 * (size_t)ND, i, a2);
                ld4(g_karr + 3 * (size_t)ND, i, a3);
                ld4(g_karr + 4 * (size_t)ND, i, a4);
                ld4(g_karr + 5 * (size_t)ND, i, a5);
                ld4(g_karr + 6 * (size_t)ND, i, a6);
                #pragma unroll
                for (int c = 0; c < 4; c++) {
                    float e = dt * (c_ce[0] * a0[c] + c_ce[1] * a2[c] + c_ce[2] * a3[c]
                                  + c_ce[3] * a4[c] + c_ce[4] * a5[c] + c_ce[5] * a6[c]);
                    mv[c] = yv[c] + dt * (c_cm[0] * a0[c] + c_cm[1] * a2[c] + c_cm[2] * a3[c]
                                        + c_cm[3] * a4[c] + c_cm[4] * a5[c] + c_cm[5] * a6[c]);
                    float tol = ATOL + RTOL * fmaxf(fabsf(yv[c]), fabsf(y1v[c]));
                    float r = e / tol;
                    local += (double)r * (double)r;
                }
                st4(g_ymid, i, mv);
            }
            local = block_reduce(local);
            if (threadIdx.x == 0) { g_red0[blockIdx.x] = local; }
        }
        grid_sync();

        // controller (block 0)
        if (blockIdx.x == 0) {
            double s = sum_partials(g_red0);
            if (threadIdx.x == 0) {
                float E2 = (float)(s / (double)ND);
                float ratio = sqrtf(E2);
                int acc_flag = (ratio <= 1.0f) ? 1 : 0;
                float dfac = (ratio < 1.0f) ? 1.0f : 0.2f;
                float factor = fminf(10.0f, fmaxf(0.9f * powf(ratio, -0.2f), dfac));
                float newdt = (ratio == 0.0f) ? g_dt * 10.0f : g_dt * factor;
                if (acc_flag) {
                    g_dt_used = g_dt;
                    g_last_t = g_t;
                    g_t = g_t + g_dt;
                    if (g_t >= TARGET) { g_done = 1; }
                }
                g_dt = newdt;
                g_accept = acc_flag;
            }
        }
        grid_sync();

        // accept: interp poly, y <- y1, k0 <- k6 (FSAL)
        if (g_accept) {
            float dtu = g_dt_used;
            for (int i = gtid; i < NV4; i += gstride) {
                float ya[4];
                float yb[4];
                float ym[4];
                float fa[4];
                float fb[4];
                float pA[4];
                float pB[4];
                float pC[4];
                float pD[4];
                float pE[4];
                ld4(g_y, i, ya);
                ld4(g_y1, i, yb);
                ld4(g_ymid, i, ym);
                ld4(g_karr + 0 * (size_t)ND, i, fa);
                ld4(g_karr + 6 * (size_t)ND, i, fb);
                #pragma unroll
                for (int c = 0; c < 4; c++) {
                    float dy0 = fa[c] * dtu;
                    float dy1 = fb[c] * dtu;
                    pA[c] = -2.f * dy0 + 2.f * dy1 - 8.f * ya[c] - 8.f * yb[c] + 16.f * ym[c];
                    pB[c] =  5.f * dy0 - 3.f * dy1 + 18.f * ya[c] + 14.f * yb[c] - 32.f * ym[c];
                    pC[c] = -4.f * dy0 + dy1 - 11.f * ya[c] - 5.f * yb[c] + 16.f * ym[c];
                    pD[c] = dy0;
                    pE[c] = ya[c];
                }
                st4(g_cA, i, pA);
                st4(g_cB, i, pB);
                st4(g_cC, i, pC);
                st4(g_cD, i, pD);
                st4(g_cE, i, pE);
                st4(g_y, i, yb);
                st4(g_karr + 0 * (size_t)ND, i, fb);
            }
        }
        grid_sync();
    }

    // dense-output interpolation at t = 1
    {
        float xr = (TARGET - g_last_t) / (g_t - g_last_t);
        for (int i = gtid; i < NV4; i += gstride) {
            float pA[4];
            float pB[4];
            float pC[4];
            float pD[4];
            float pE[4];
            float o[4];
            ld4(g_cA, i, pA);
            ld4(g_cB, i, pB);
            ld4(g_cC, i, pC);
            ld4(g_cD, i, pD);
            ld4(g_cE, i, pE);
            #pragma unroll
            for (int c = 0; c < 4; c++) {
                o[c] = (((pA[c] * xr + pB[c]) * xr + pC[c]) * xr + pD[c]) * xr + pE[c];
            }
            st4(out, i, o);
        }
    }
}

// ---------------- host: ONE launch -------------------------------------------
extern "C" void kernel_launch(void* const* d_in, const int* in_sizes, int n_in,
                              void* d_out, int out_size)
{
    const float* x  = (const float*)d_in[0];
    const float* W1 = (const float*)d_in[1];
    const float* b1 = (const float*)d_in[2];
    const float* W2 = (const float*)d_in[3];
    const float* b2 = (const float*)d_in[4];
    const float* W3 = (const float*)d_in[5];
    const float* b3 = (const float*)d_in[6];
    float* out = (float*)d_out;

    cudaFuncSetAttribute(solver_kernel,
                         cudaFuncAttributeMaxDynamicSharedMemorySize, DSM_BYTES);
    solver_kernel<<<GRIDX, NT, DSM_BYTES>>>(x, W1, b1, W2, b2, W3, b3, out);
}

// round 17
// speedup vs baseline: 1.1346x; 1.0509x over previous
#include <cuda_runtime.h>
#include <cuda_bf16.h>
#include <cstdint>
#include <math.h>

// Problem shape
constexpr int B = 8192, D = 1024, H = 2048;
constexpr int ND = B * D;
constexpr int NV4 = ND / 4;
constexpr float RTOL = 1e-3f, ATOL = 1e-3f, TARGET = 1.0f;
constexpr int NT = 256;
constexpr int GRIDX = 296;
constexpr int MAXSTEPS = 1000;

// dynamic SMEM layout (per pipeline stage)
constexpr int SA_H_OFF = 0;          // A hi: 128 rows * 80B
constexpr int SA_L_OFF = 10240;      // A lo
constexpr int SW_H_OFF = 20480;      // W hi: 32 rows * 272B
constexpr int SW_L_OFF = 29184;      // W lo
constexpr int STAGE_BYTES = 37888;   // total per stage
constexpr int DSM_BYTES = 2 * STAGE_BYTES;  // 75776

// ---------------- device state (static; no allocations) --------------------
__device__ float g_y[ND], g_y1[ND], g_ymid[ND];
__device__ float g_karr[7 * ND];
__device__ float g_cA[ND], g_cB[ND], g_cC[ND], g_cD[ND], g_cE[ND];
__device__ double g_red0[GRIDX], g_red1[GRIDX];
__device__ float g_t, g_dt, g_last_t, g_dt_used, g_h0, g_d1;
__device__ int   g_done, g_accept;
__device__ unsigned g_bar_count;
__device__ volatile unsigned g_bar_gen;

// bf16 hi/lo split storage
__device__ __nv_bfloat16 g_W1h[D * H], g_W1l[D * H];
__device__ __nv_bfloat16 g_W2h[H * H], g_W2l[H * H];
__device__ __nv_bfloat16 g_W3h[H * D], g_W3l[H * D];
__device__ __nv_bfloat16 g_xh[ND], g_xl[ND];
__device__ __nv_bfloat16 g_h1h[B * H], g_h1l[B * H];
__device__ __nv_bfloat16 g_h2h[B * H], g_h2l[B * H];

__constant__ float c_beta[6][6] = {
  {0.2f, 0.f, 0.f, 0.f, 0.f, 0.f},
  {(float)(3.0/40.0), (float)(9.0/40.0), 0.f, 0.f, 0.f, 0.f},
  {(float)(44.0/45.0), (float)(-56.0/15.0), (float)(32.0/9.0), 0.f, 0.f, 0.f},
  {(float)(19372.0/6561.0), (float)(-25360.0/2187.0), (float)(64448.0/6561.0),
   (float)(-212.0/729.0), 0.f, 0.f},
  {(float)(9017.0/3168.0), (float)(-355.0/33.0), (float)(46732.0/5247.0),
   (float)(49.0/176.0), (float)(-5103.0/18656.0), 0.f},
  {(float)(35.0/384.0), 0.f, (float)(500.0/1113.0), (float)(125.0/192.0),
   (float)(-2187.0/6784.0), (float)(11.0/84.0)},
};
__constant__ float c_ce[6] = {
  (float)(35.0/384.0 - 1951.0/21600.0),
  (float)(500.0/1113.0 - 22642.0/50085.0),
  (float)(125.0/192.0 - 451.0/720.0),
  (float)(-2187.0/6784.0 + 12231.0/42400.0),
  (float)(11.0/84.0 - 649.0/6300.0),
  (float)(-1.0/60.0),
};
__constant__ float c_cm[6] = {
  (float)(6025192743.0/30085553152.0/2.0),
  (float)(51252292925.0/65400821598.0/2.0),
  (float)(-2691868925.0/45128329728.0/2.0),
  (float)(187940372067.0/1594534317056.0/2.0),
  (float)(-1776094331.0/19743644256.0/2.0),
  (float)(11237099.0/235043384.0/2.0),
};

// ---------------- small helpers ---------------------------------------------
__device__ __forceinline__ void ld4(const float* p, int i, float* o) {
    float4 t = ((const float4*)p)[i];
    o[0] = t.x; o[1] = t.y; o[2] = t.z; o[3] = t.w;
}
__device__ __forceinline__ void st4(float* p, int i, const float* o) {
    float4 t;
    t.x = o[0]; t.y = o[1]; t.z = o[2]; t.w = o[3];
    ((float4*)p)[i] = t;
}

__device__ __forceinline__ unsigned smem_u32(const void* p) {
    unsigned r;
    asm("{ .reg .u64 t; cvta.to.shared.u64 t, %1; cvt.u32.u64 %0, t; }"
        : "=r"(r) : "l"(p));
    return r;
}

// ---------------- software grid barrier -------------------------------------
__device__ __forceinline__ void grid_sync() {
    __threadfence();
    __syncthreads();
    if (threadIdx.x == 0) {
        unsigned gen = g_bar_gen;
        if (atomicAdd(&g_bar_count, 1u) == gridDim.x - 1) {
            g_bar_count = 0;
            __threadfence();
            g_bar_gen = gen + 1;
        } else {
            while (g_bar_gen == gen) { __nanosleep(64); }
        }
    }
    __syncthreads();
    __threadfence();
}

// ---------------- tensor-core / cp.async primitives --------------------------
__device__ __forceinline__ void ldsm4(unsigned* r, unsigned addr) {
    asm volatile("ldmatrix.sync.aligned.m8n8.x4.shared.b16 {%0,%1,%2,%3}, [%4];"
                 : "=r"(r[0]), "=r"(r[1]), "=r"(r[2]), "=r"(r[3]) : "r"(addr));
}
__device__ __forceinline__ void ldsm4t(unsigned* r, unsigned addr) {
    asm volatile("ldmatrix.sync.aligned.m8n8.x4.trans.shared.b16 {%0,%1,%2,%3}, [%4];"
                 : "=r"(r[0]), "=r"(r[1]), "=r"(r[2]), "=r"(r[3]) : "r"(addr));
}
__device__ __forceinline__ void mma_bf16(float* d, const unsigned* a, const unsigned* b) {
    asm volatile(
        "mma.sync.aligned.m16n8k16.row.col.f32.bf16.bf16.f32 "
        "{%0,%1,%2,%3}, {%4,%5,%6,%7}, {%8,%9}, {%0,%1,%2,%3};"
        : "+f"(d[0]), "+f"(d[1]), "+f"(d[2]), "+f"(d[3])
        : "r"(a[0]), "r"(a[1]), "r"(a[2]), "r"(a[3]), "r"(b[0]), "r"(b[1]));
}
__device__ __forceinline__ void cp16(unsigned sa, const void* g) {
    asm volatile("cp.async.cg.shared.global [%0], [%1], 16;" :: "r"(sa), "l"(g));
}
__device__ __forceinline__ void cp_commit() {
    asm volatile("cp.async.commit_group;");
}
__device__ __forceinline__ void cp_wait1() {
    asm volatile("cp.async.wait_group 1;");
}
__device__ __forceinline__ void cp_wait0() {
    asm volatile("cp.async.wait_group 0;");
}

// issue async loads for one 32-wide K block into pipeline stage at sbase
__device__ __forceinline__ void issue_tile(
    const __nv_bfloat16* Ah, const __nv_bfloat16* Al,
    const __nv_bfloat16* Wh, const __nv_bfloat16* Wl,
    int bm, int bn, int kb, int K, int N, unsigned sbase, int tid)
{
    #pragma unroll
    for (int half = 0; half < 2; half++) {
        const int t = tid + half * 256;
        const int arow = t >> 2;
        const int ac4 = t & 3;
        const size_t aoff = (size_t)(bm + arow) * K + kb + ac4 * 8;
        cp16(sbase + SA_H_OFF + arow * 80 + ac4 * 16, Ah + aoff);
        cp16(sbase + SA_L_OFF + arow * 80 + ac4 * 16, Al + aoff);
        const int wrow = t >> 4;
        const int wcc = t & 15;
        const size_t woff = (size_t)(kb + wrow) * N + bn + wcc * 8;
        cp16(sbase + SW_H_OFF + wrow * 272 + wcc * 16, Wh + woff);
        cp16(sbase + SW_L_OFF + wrow * 272 + wcc * 16, Wl + woff);
    }
    cp_commit();
}

// ---------------- bf16-split GEMM phase (cp.async double-buffered) ----------
// C[M,N] = (Ah+Al)[M,K] @ (Wh+Wl)[K,N] + bias (+ReLU)
// Warp grid 4(M) x 2(N), warp tile 32x64 (R11 layout).
// B fragments loaded with ldmatrix.x4.trans (k16 x n16 per instruction).
__device__ void gemm_tc(const __nv_bfloat16* Ah, const __nv_bfloat16* Al,
                        const __nv_bfloat16* Wh, const __nv_bfloat16* Wl,
                        const float* bias, float* Cf,
                        __nv_bfloat16* Ch, __nv_bfloat16* Cl,
                        int M, int N, int K, int relu)
{
    extern __shared__ char dsm[];
    const unsigned dbase = smem_u32(dsm);

    const int tid = threadIdx.x;
    const int lane = tid & 31;
    const int wrp = tid >> 5;
    const int warp_m = wrp >> 1;
    const int warp_n = wrp & 1;
    const int m_base = warp_m * 32;
    const int n_base = warp_n * 64;
    const int lrow = lane & 15;
    const int lcolh = (lane >> 4) << 3;
    const int nsel = lane >> 4;          // 0 for lanes 0-15, 1 for 16-31

    const int ntn = N >> 7;
    const int ntiles = (M >> 7) * ntn;

    for (int tile = blockIdx.x; tile < ntiles; tile += gridDim.x) {
        const int bm = (tile / ntn) << 7;
        const int bn = (tile % ntn) << 7;

        float acc[2][8][4];
        #pragma unroll
        for (int mt = 0; mt < 2; mt++) {
            #pragma unroll
            for (int nt = 0; nt < 8; nt++) {
                #pragma unroll
                for (int q = 0; q < 4; q++) { acc[mt][nt][q] = 0.f; }
            }
        }

        issue_tile(Ah, Al, Wh, Wl, bm, bn, 0, K, N, dbase, tid);

        for (int kb = 0; kb < K; kb += 32) {
            const int st = (kb >> 5) & 1;
            const unsigned sb = dbase + st * STAGE_BYTES;
            if (kb + 32 < K) {
                issue_tile(Ah, Al, Wh, Wl, bm, bn, kb + 32, K, N,
                           dbase + (st ^ 1) * STAGE_BYTES, tid);
                cp_wait1();
            } else {
                cp_wait0();
            }
            __syncthreads();

            #pragma unroll
            for (int kh = 0; kh < 32; kh += 16) {
                unsigned rah[2][4];
                unsigned ral[2][4];
                #pragma unroll
                for (int mt = 0; mt < 2; mt++) {
                    const unsigned off =
                        (unsigned)(((m_base + mt * 16 + lrow) * 40 + kh + lcolh) * 2);
                    ldsm4(rah[mt], sb + SA_H_OFF + off);
                    ldsm4(ral[mt], sb + SA_L_OFF + off);
                }
                #pragma unroll
                for (int nt2 = 0; nt2 < 8; nt2 += 2) {
                    // x4.trans: lanes 0-15 address rows of n-half 0, lanes 16-31
                    // the same rows of n-half 1 (+16B). Yields k16 x n16:
                    // {r0,r1} = B frag for column nt2, {r2,r3} = for nt2+1.
                    const unsigned boff =
                        (unsigned)(((kh + lrow) * 136 + n_base + nt2 * 8 + nsel * 8) * 2);
                    unsigned rbh[4];
                    unsigned rbl[4];
                    ldsm4t(rbh, sb + SW_H_OFF + boff);
                    ldsm4t(rbl, sb + SW_L_OFF + boff);
                    #pragma unroll
                    for (int mt = 0; mt < 2; mt++) {
                        mma_bf16(acc[mt][nt2], rah[mt], rbh + 0);
                        mma_bf16(acc[mt][nt2], rah[mt], rbl + 0);
                        mma_bf16(acc[mt][nt2], ral[mt], rbh + 0);
                        mma_bf16(acc[mt][nt2 + 1], rah[mt], rbh + 2);
                        mma_bf16(acc[mt][nt2 + 1], rah[mt], rbl + 2);
                        mma_bf16(acc[mt][nt2 + 1], ral[mt], rbh + 2);
                    }
                }
            }
            __syncthreads();
        }

        const int er = lane >> 2;
        const int ec = (lane & 3) << 1;
        #pragma unroll
        for (int mt = 0; mt < 2; mt++) {
            #pragma unroll
            for (int nt = 0; nt < 8; nt++) {
                const int col = bn + n_base + nt * 8 + ec;
                const float bx = bias[col];
                const float by = bias[col + 1];
                #pragma unroll
                for (int hr = 0; hr < 2; hr++) {
                    const int row = bm + m_base + mt * 16 + er + hr * 8;
                    float v0 = acc[mt][nt][hr * 2 + 0] + bx;
                    float v1 = acc[mt][nt][hr * 2 + 1] + by;
                    if (relu) { v0 = fmaxf(v0, 0.f); v1 = fmaxf(v1, 0.f); }
                    if (Cf) {
                        *(float2*)(Cf + (size_t)row * N + col) = make_float2(v0, v1);
                    } else {
                        __nv_bfloat162 hv = __floats2bfloat162_rn(v0, v1);
                        float l0 = v0 - __bfloat162float(hv.x);
                        float l1 = v1 - __bfloat162float(hv.y);
                        *(__nv_bfloat162*)(Ch + (size_t)row * N + col) = hv;
                        *(__nv_bfloat162*)(Cl + (size_t)row * N + col) =
                            __floats2bfloat162_rn(l0, l1);
                    }
                }
            }
        }
    }
}

// f(split stage vec in g_xh/g_xl) -> kout (fp32)
__device__ void eval_f(float* kout, const float* b1, const float* b2, const float* b3)
{
    gemm_tc(g_xh, g_xl, g_W1h, g_W1l, b1, (float*)0, g_h1h, g_h1l, B, H, D, 1);
    grid_sync();
    gemm_tc(g_h1h, g_h1l, g_W2h, g_W2l, b2, (float*)0, g_h2h, g_h2l, B, H, H, 1);
    grid_sync();
    gemm_tc(g_h2h, g_h2l, g_W3h, g_W3l, b3, kout, (__nv_bfloat16*)0, (__nv_bfloat16*)0, B, D, H, 0);
    grid_sync();
}

// split float[4] into hi/lo bf16 at float4-index i of g_xh/g_xl
__device__ __forceinline__ void store_split(int i, const float* o) {
    __nv_bfloat162 h0 = __floats2bfloat162_rn(o[0], o[1]);
    __nv_bfloat162 h1 = __floats2bfloat162_rn(o[2], o[3]);
    __nv_bfloat162 l0 = __floats2bfloat162_rn(o[0] - __bfloat162float(h0.x),
                                              o[1] - __bfloat162float(h0.y));
    __nv_bfloat162 l1 = __floats2bfloat162_rn(o[2] - __bfloat162float(h1.x),
                                              o[3] - __bfloat162float(h1.y));
    ((__nv_bfloat162*)g_xh)[2 * i]     = h0;
    ((__nv_bfloat162*)g_xh)[2 * i + 1] = h1;
    ((__nv_bfloat162*)g_xl)[2 * i]     = l0;
    ((__nv_bfloat162*)g_xl)[2 * i + 1] = l1;
}

__device__ double block_reduce(double v) {
    __shared__ double sh[NT];
    sh[threadIdx.x] = v;
    __syncthreads();
    for (int s = NT / 2; s > 0; s >>= 1) {
        if (threadIdx.x < s) { sh[threadIdx.x] += sh[threadIdx.x + s]; }
        __syncthreads();
    }
    double r = sh[0];
    __syncthreads();
    return r;
}

__device__ double sum_partials(const double* part) {
    double s = 0.0;
    for (int i = threadIdx.x; i < (int)gridDim.x; i += NT) { s += part[i]; }
    return block_reduce(s);
}

__device__ void split_weights(const float* W, __nv_bfloat16* Wh, __nv_bfloat16* Wl,
                              int n, int gtid, int gstride)
{
    for (int i = gtid; i < n; i += gstride) {
        float w = W[i];
        __nv_bfloat16 h = __float2bfloat16(w);
        Wh[i] = h;
        Wl[i] = __float2bfloat16(w - __bfloat162float(h));
    }
}

// ---------------- the whole dopri5 solver as ONE kernel ---------------------
__global__ __launch_bounds__(NT, 2) void solver_kernel(
    const float* __restrict__ x,
    const float* __restrict__ W1, const float* __restrict__ b1,
    const float* __restrict__ W2, const float* __restrict__ b2,
    const float* __restrict__ W3, const float* __restrict__ b3,
    float* __restrict__ out)
{
    const int gtid = blockIdx.x * NT + threadIdx.x;
    const int gstride = gridDim.x * NT;

    // weights -> bf16 hi/lo; y = x (+ split)
    split_weights(W1, g_W1h, g_W1l, D * H, gtid, gstride);
    split_weights(W2, g_W2h, g_W2l, H * H, gtid, gstride);
    split_weights(W3, g_W3h, g_W3l, H * D, gtid, gstride);
    for (int i = gtid; i < NV4; i += gstride) {
        float v[4];
        ld4(x, i, v);
        st4(g_y, i, v);
        store_split(i, v);
    }
    grid_sync();

    // f0 = f(y) -> k0
    eval_f(g_karr, b1, b2, b3);

    // d0, d1 partials
    {
        double s0 = 0.0;
        double s1 = 0.0;
        for (int i = gtid; i < NV4; i += gstride) {
            float yv[4];
            float fv[4];
            ld4(g_y, i, yv);
            ld4(g_karr, i, fv);
            #pragma unroll
            for (int c = 0; c < 4; c++) {
                float sc = ATOL + RTOL * fabsf(yv[c]);
                float r0 = yv[c] / sc;
                float r1 = fv[c] / sc;
                s0 += (double)r0 * r0;
                s1 += (double)r1 * r1;
            }
        }
        s0 = block_reduce(s0);
        s1 = block_reduce(s1);
        if (threadIdx.x == 0) { g_red0[blockIdx.x] = s0; g_red1[blockIdx.x] = s1; }
    }
    grid_sync();
    if (blockIdx.x == 0) {
        double s0 = sum_partials(g_red0);
        double s1 = sum_partials(g_red1);
        if (threadIdx.x == 0) {
            float d0 = sqrtf((float)s0);
            float d1 = sqrtf((float)s1);
            g_d1 = d1;
            g_h0 = (d0 < 1e-5f || d1 < 1e-5f) ? 1e-6f : 0.01f * d0 / d1;
        }
    }
    grid_sync();

    // stage vec = y + h0*f0 ; f1 -> k1 slot
    {
        float h0v = g_h0;
        for (int i = gtid; i < NV4; i += gstride) {
            float yv[4];
            float fv[4];
            float o[4];
            ld4(g_y, i, yv);
            ld4(g_karr, i, fv);
            #pragma unroll
            for (int c = 0; c < 4; c++) { o[c] = yv[c] + h0v * fv[c]; }
            store_split(i, o);
        }
    }
    grid_sync();
    eval_f(g_karr + (size_t)ND, b1, b2, b3);

    // d2 -> initial dt
    {
        double s = 0.0;
        for (int i = gtid; i < NV4; i += gstride) {
            float yv[4];
            float fa[4];
            float fb[4];
            ld4(g_y, i, yv);
            ld4(g_karr, i, fa);
            ld4(g_karr + (size_t)ND, i, fb);
            #pragma unroll
            for (int c = 0; c < 4; c++) {
                float sc = ATOL + RTOL * fabsf(yv[c]);
                float r = (fb[c] - fa[c]) / sc;
                s += (double)r * r;
            }
        }
        s = block_reduce(s);
        if (threadIdx.x == 0) { g_red0[blockIdx.x] = s; }
    }
    grid_sync();
    if (blockIdx.x == 0) {
        double s = sum_partials(g_red0);
        if (threadIdx.x == 0) {
            float d2 = sqrtf((float)s) / g_h0;
            float d1 = g_d1;
            float h1v;
            if (d1 <= 1e-15f && d2 <= 1e-15f) {
                h1v = fmaxf(1e-6f, g_h0 * 1e-3f);
            } else {
                h1v = powf(0.01f / fmaxf(d1, d2), 0.2f);
            }
            g_dt = fminf(100.f * g_h0, h1v);
            g_t = 0.f; g_last_t = 0.f; g_done = 0; g_accept = 0;
        }
    }
    grid_sync();

    // adaptive loop
    for (int step = 0; step < MAXSTEPS; step++) {
        if (g_done) { break; }

        for (int s = 0; s < 6; s++) {
            float dt = g_dt;
            for (int i = gtid; i < NV4; i += gstride) {
                float accv[4] = {0.f, 0.f, 0.f, 0.f};
                for (int j = 0; j <= s; j++) {
                    float cj = c_beta[s][j];
                    float kv[4];
                    ld4(g_karr + (size_t)j * ND, i, kv);
                    #pragma unroll
                    for (int c = 0; c < 4; c++) { accv[c] += cj * kv[c]; }
                }
                float yv[4];
                float o[4];
                ld4(g_y, i, yv);
                #pragma unroll
                for (int c = 0; c < 4; c++) { o[c] = yv[c] + dt * accv[c]; }
                store_split(i, o);
                if (s == 5) { st4(g_y1, i, o); }
            }
            grid_sync();
            eval_f(g_karr + (size_t)(s + 1) * ND, b1, b2, b3);
        }

        // combine: error partials + y_mid
        {
            float dt = g_dt;
            double local = 0.0;
            for (int i = gtid; i < NV4; i += gstride) {
                float yv[4];
                float y1v[4];
                float mv[4];
                float a0[4];
                float a2[4];
                float a3[4];
                float a4[4];
                float a5[4];
                float a6[4];
                ld4(g_y, i, yv);
                ld4(g_y1, i, y1v);
                ld4(g_karr + 0 * (size_t)ND, i, a0);
                ld4(g_karr + 2 * (size_t)ND, i, a2);
                ld4(g_karr + 3 * (size_t)ND, i, a3);
                ld4(g_karr + 4 * (size_t)ND, i, a4);
                ld4(g_karr + 5 * (size_t)ND, i, a5);
                ld4(g_karr + 6 * (size_t)ND, i, a6);
                #pragma unroll
                for (int c = 0; c < 4; c++) {
                    float e = dt * (c_ce[0] * a0[c] + c_ce[1] * a2[c] + c_ce[2] * a3[c]
                                  + c_ce[3] * a4[c] + c_ce[4] * a5[c] + c_ce[5] * a6[c]);
                    mv[c] = yv[c] + dt * (c_cm[0] * a0[c] + c_cm[1] * a2[c] + c_cm[2] * a3[c]
                                        + c_cm[3] * a4[c] + c_cm[4] * a5[c] + c_cm[5] * a6[c]);
                    float tol = ATOL + RTOL * fmaxf(fabsf(yv[c]), fabsf(y1v[c]));
                    float r = e / tol;
                    local += (double)r * (double)r;
                }
                st4(g_ymid, i, mv);
            }
            local = block_reduce(local);
            if (threadIdx.x == 0) { g_red0[blockIdx.x] = local; }
        }
        grid_sync();

        // controller (block 0)
        if (blockIdx.x == 0) {
            double s = sum_partials(g_red0);
            if (threadIdx.x == 0) {
                float E2 = (float)(s / (double)ND);
                float ratio = sqrtf(E2);
                int acc_flag = (ratio <= 1.0f) ? 1 : 0;
                float dfac = (ratio < 1.0f) ? 1.0f : 0.2f;
                float factor = fminf(10.0f, fmaxf(0.9f * powf(ratio, -0.2f), dfac));
                float newdt = (ratio == 0.0f) ? g_dt * 10.0f : g_dt * factor;
                if (acc_flag) {
                    g_dt_used = g_dt;
                    g_last_t = g_t;
                    g_t = g_t + g_dt;
                    if (g_t >= TARGET) { g_done = 1; }
                }
                g_dt = newdt;
                g_accept = acc_flag;
            }
        }
        grid_sync();

        // accept: interp poly, y <- y1, k0 <- k6 (FSAL)
        if (g_accept) {
            float dtu = g_dt_used;
            for (int i = gtid; i < NV4; i += gstride) {
                float ya[4];
                float yb[4];
                float ym[4];
                float fa[4];
                float fb[4];
                float pA[4];
                float pB[4];
                float pC[4];
                float pD[4];
                float pE[4];
                ld4(g_y, i, ya);
                ld4(g_y1, i, yb);
                ld4(g_ymid, i, ym);
                ld4(g_karr + 0 * (size_t)ND, i, fa);
                ld4(g_karr + 6 * (size_t)ND, i, fb);
                #pragma unroll
                for (int c = 0; c < 4; c++) {
                    float dy0 = fa[c] * dtu;
                    float dy1 = fb[c] * dtu;
                    pA[c] = -2.f * dy0 + 2.f * dy1 - 8.f * ya[c] - 8.f * yb[c] + 16.f * ym[c];
                    pB[c] =  5.f * dy0 - 3.f * dy1 + 18.f * ya[c] + 14.f * yb[c] - 32.f * ym[c];
                    pC[c] = -4.f * dy0 + dy1 - 11.f * ya[c] - 5.f * yb[c] + 16.f * ym[c];
                    pD[c] = dy0;
                    pE[c] = ya[c];
                }
                st4(g_cA, i, pA);
                st4(g_cB, i, pB);
                st4(g_cC, i, pC);
                st4(g_cD, i, pD);
                st4(g_cE, i, pE);
                st4(g_y, i, yb);
                st4(g_karr + 0 * (size_t)ND, i, fb);
            }
        }
        grid_sync();
    }

    // dense-output interpolation at t = 1
    {
        float xr = (TARGET - g_last_t) / (g_t - g_last_t);
        for (int i = gtid; i < NV4; i += gstride) {
            float pA[4];
            float pB[4];
            float pC[4];
            float pD[4];
            float pE[4];
            float o[4];
            ld4(g_cA, i, pA);
            ld4(g_cB, i, pB);
            ld4(g_cC, i, pC);
            ld4(g_cD, i, pD);
            ld4(g_cE, i, pE);
            #pragma unroll
            for (int c = 0; c < 4; c++) {
                o[c] = (((pA[c] * xr + pB[c]) * xr + pC[c]) * xr + pD[c]) * xr + pE[c];
            }
            st4(out, i, o);
        }
    }
}

// ---------------- host: ONE launch -------------------------------------------
extern "C" void kernel_launch(void* const* d_in, const int* in_sizes, int n_in,
                              void* d_out, int out_size)
{
    const float* x  = (const float*)d_in[0];
    const float* W1 = (const float*)d_in[1];
    const float* b1 = (const float*)d_in[2];
    const float* W2 = (const float*)d_in[3];
    const float* b2 = (const float*)d_in[4];
    const float* W3 = (const float*)d_in[5];
    const float* b3 = (const float*)d_in[6];
    float* out = (float*)d_out;

    cudaFuncSetAttribute(solver_kernel,
                         cudaFuncAttributeMaxDynamicSharedMemorySize, DSM_BYTES);
    solver_kernel<<<GRIDX, NT, DSM_BYTES>>>(x, W1, b1, W2, b2, W3, b3, out);
}